// round 12
// baseline (speedup 1.0000x reference)
#include <cuda_runtime.h>

// Shape: a, b, h : (B=2, S=2048, D=1024, N=16) fp32, row-major.
// h[t] = a[t]*h[t-1] + b[t] along S. B*D*N = 32768 independent channels,
// contiguous at fixed t; scan stride = D*N = 16384 floats.
//
// R11: R10 mechanism (demand __ldcs pipeline U=8/distance-4 + per-line
// prefetch.global.L2 at lead 12 groups) with two deltas:
//   - block=128 / grid=256: covers all 148 SMs (recovers the 77% DRAM seen
//     at grid=512) while keeping block count moderate (small replay gap)
//   - st.global.wt output stores: write-through leaves no dirty lines in L2,
//     so the next graph replay doesn't pay an eviction/writeback collision
//     at its read-heavy start (the hypothesized source of the wall-vs-ncu
//     gap that only prefetch kernels exhibit)

static constexpr int S_LEN   = 2048;
static constexpr int STRIDE  = 1024 * 16;       // D*N floats between timesteps
static constexpr int CHANNELS = 2 * STRIDE;     // 32768
static constexpr int U       = 8;               // timesteps per group
static constexpr int N_GROUPS = S_LEN / U;      // 256
static constexpr int N_SUPER  = N_GROUPS / 8;   // 32 super-iterations
static constexpr int BLOCK   = 128;
static constexpr int PF_G    = 12;              // prefetch lead base (groups)

// Demand-load local group G (relative to current ap/bp) into buffers A/B.
#define PREF(A, B, G)                                            \
    _Pragma("unroll")                                            \
    for (int u = 0; u < U; u++) {                                \
        A[u] = __ldcs(ap + ((G) * U + u) * STRIDE);              \
        B[u] = __ldcs(bp + ((G) * U + u) * STRIDE);              \
    }

// Consume buffers A/B as local group G: serial FMA chain + write-through
// stores (no dirty L2 lines left behind for the next replay).
#define CONS(A, B, G)                                            \
    _Pragma("unroll")                                            \
    for (int u = 0; u < U; u++) {                                \
        h = fmaf(A[u], h, B[u]);                                 \
        asm volatile("st.global.wt.f32 [%0], %1;" ::             \
            "l"(op + ((G) * U + u) * STRIDE), "f"(h) : "memory");\
    }

// Per-line L2 prefetch of local group G (pfa/pfb pre-advanced by PF_G groups).
#define PFL2(G)                                                  \
    if ((s * 8 + (G)) < N_GROUPS) {                              \
        _Pragma("unroll")                                        \
        for (int u = 0; u < U; u++) {                            \
            asm volatile("prefetch.global.L2 [%0];" ::           \
                "l"(pfa + (((G) - PF_G) * U + u) * STRIDE));     \
            asm volatile("prefetch.global.L2 [%0];" ::           \
                "l"(pfb + (((G) - PF_G) * U + u) * STRIDE));     \
        }                                                        \
    }

__global__ __launch_bounds__(BLOCK, 2)
void ParallelScan_37374805409922_kernel(const float* __restrict__ a,
                                        const float* __restrict__ b,
                                        float* __restrict__ out) {
    const int idx   = blockIdx.x * BLOCK + threadIdx.x;        // 0..32767
    const int batch = idx >> 14;                               // / 16384
    const int col   = idx & (STRIDE - 1);
    const size_t base = (size_t)batch * S_LEN * STRIDE + col;

    const float* __restrict__ ap = a + base;
    const float* __restrict__ bp = b + base;
    float* __restrict__ op = out + base;

    const float* pfa = ap + PF_G * U * STRIDE;
    const float* pfb = bp + PF_G * U * STRIDE;

    float a0[U], b0[U], a1[U], b1[U], a2[U], b2[U], a3[U], b3[U];
    float a4[U], b4[U], a5[U], b5[U], a6[U], b6[U], a7[U], b7[U];
    float h = 0.0f;

    // Prologue: demand-load 4 groups (prefetch window warms up organically).
    PREF(a0, b0, 0)
    PREF(a1, b1, 1)
    PREF(a2, b2, 2)
    PREF(a3, b3, 3)

    #pragma unroll 1
    for (int s = 0; s < N_SUPER; s++) {
        // Each slot: L2-prefetch 12 groups ahead, demand-load 4 ahead,
        // consume current.
        PFL2(12)  PREF(a4, b4, 4)  CONS(a0, b0, 0)
        PFL2(13)  PREF(a5, b5, 5)  CONS(a1, b1, 1)
        PFL2(14)  PREF(a6, b6, 6)  CONS(a2, b2, 2)
        PFL2(15)  PREF(a7, b7, 7)  CONS(a3, b3, 3)

        if (s + 1 < N_SUPER) {
            PFL2(16)  PREF(a0, b0, 8)   CONS(a4, b4, 4)
            PFL2(17)  PREF(a1, b1, 9)   CONS(a5, b5, 5)
            PFL2(18)  PREF(a2, b2, 10)  CONS(a6, b6, 6)
            PFL2(19)  PREF(a3, b3, 11)  CONS(a7, b7, 7)
        } else {
            CONS(a4, b4, 4)
            CONS(a5, b5, 5)
            CONS(a6, b6, 6)
            CONS(a7, b7, 7)
        }

        ap  += 8 * U * STRIDE;
        bp  += 8 * U * STRIDE;
        op  += 8 * U * STRIDE;
        pfa += 8 * U * STRIDE;
        pfb += 8 * U * STRIDE;
    }
}

extern "C" void kernel_launch(void* const* d_in, const int* in_sizes, int n_in,
                              void* d_out, int out_size) {
    const float* a = (const float*)d_in[0];
    const float* b = (const float*)d_in[1];
    float* out = (float*)d_out;
    (void)in_sizes; (void)n_in; (void)out_size;

    ParallelScan_37374805409922_kernel<<<CHANNELS / BLOCK, BLOCK>>>(a, b, out);
}

// round 14
// speedup vs baseline: 1.0299x; 1.0299x over previous
#include <cuda_runtime.h>

// Shape: a, b, h : (B=2, S=2048, D=1024, N=16) fp32, row-major.
// h[t] = a[t]*h[t-1] + b[t] along S. B*D*N = 32768 independent channels,
// contiguous at fixed t; scan stride = D*N = 16384 floats.
//
// R12: one CTA per SM AND full SM coverage.
//   - block=224 (7 warps), grid=147: 147 CTAs -> exactly 1 CTA/SM on 147 of
//     148 SMs. Gap table (R6-R11) shows the wall-vs-ncu replay gap is a
//     multi-CTA-per-SM phenomenon (cross-CTA L1tex contention, spread):
//     1 CTA/SM shapes gap 2.5-3.6 us, >=2 CTA/SM shapes gap 14-24 us.
//     Full coverage recovers DRAM 74% -> ~79% (R11).
//   - mechanism unchanged: demand __ldcs register pipeline U=8/distance-4,
//     per-line prefetch.global.L2 at lead 12 groups, st.global.wt output
//     (best ncu on record, 120.2 us).
//   - tail guard: 147*224 = 32928 > 32768 channels; surplus threads exit.

static constexpr int S_LEN   = 2048;
static constexpr int STRIDE  = 1024 * 16;       // D*N floats between timesteps
static constexpr int CHANNELS = 2 * STRIDE;     // 32768
static constexpr int U       = 8;               // timesteps per group
static constexpr int N_GROUPS = S_LEN / U;      // 256
static constexpr int N_SUPER  = N_GROUPS / 8;   // 32 super-iterations
static constexpr int BLOCK   = 224;             // 7 warps
static constexpr int GRID    = (CHANNELS + BLOCK - 1) / BLOCK;  // 147
static constexpr int PF_G    = 12;              // prefetch lead base (groups)

// Demand-load local group G (relative to current ap/bp) into buffers A/B.
#define PREF(A, B, G)                                            \
    _Pragma("unroll")                                            \
    for (int u = 0; u < U; u++) {                                \
        A[u] = __ldcs(ap + ((G) * U + u) * STRIDE);              \
        B[u] = __ldcs(bp + ((G) * U + u) * STRIDE);              \
    }

// Consume buffers A/B as local group G: serial FMA chain + write-through
// stores.
#define CONS(A, B, G)                                            \
    _Pragma("unroll")                                            \
    for (int u = 0; u < U; u++) {                                \
        h = fmaf(A[u], h, B[u]);                                 \
        asm volatile("st.global.wt.f32 [%0], %1;" ::             \
            "l"(op + ((G) * U + u) * STRIDE), "f"(h) : "memory");\
    }

// Per-line L2 prefetch of local group G (pfa/pfb pre-advanced by PF_G groups).
#define PFL2(G)                                                  \
    if ((s * 8 + (G)) < N_GROUPS) {                              \
        _Pragma("unroll")                                        \
        for (int u = 0; u < U; u++) {                            \
            asm volatile("prefetch.global.L2 [%0];" ::           \
                "l"(pfa + (((G) - PF_G) * U + u) * STRIDE));     \
            asm volatile("prefetch.global.L2 [%0];" ::           \
                "l"(pfb + (((G) - PF_G) * U + u) * STRIDE));     \
        }                                                        \
    }

__global__ __launch_bounds__(BLOCK, 1)
void ParallelScan_37374805409922_kernel(const float* __restrict__ a,
                                        const float* __restrict__ b,
                                        float* __restrict__ out) {
    const int idx = blockIdx.x * BLOCK + threadIdx.x;          // 0..32927
    if (idx >= CHANNELS) return;                               // tail guard
    const int batch = idx >> 14;                               // / 16384
    const int col   = idx & (STRIDE - 1);
    const size_t base = (size_t)batch * S_LEN * STRIDE + col;

    const float* __restrict__ ap = a + base;
    const float* __restrict__ bp = b + base;
    float* __restrict__ op = out + base;

    const float* pfa = ap + PF_G * U * STRIDE;
    const float* pfb = bp + PF_G * U * STRIDE;

    float a0[U], b0[U], a1[U], b1[U], a2[U], b2[U], a3[U], b3[U];
    float a4[U], b4[U], a5[U], b5[U], a6[U], b6[U], a7[U], b7[U];
    float h = 0.0f;

    // Prologue: demand-load 4 groups (prefetch window warms up organically).
    PREF(a0, b0, 0)
    PREF(a1, b1, 1)
    PREF(a2, b2, 2)
    PREF(a3, b3, 3)

    #pragma unroll 1
    for (int s = 0; s < N_SUPER; s++) {
        // Each slot: L2-prefetch 12 groups ahead, demand-load 4 ahead,
        // consume current.
        PFL2(12)  PREF(a4, b4, 4)  CONS(a0, b0, 0)
        PFL2(13)  PREF(a5, b5, 5)  CONS(a1, b1, 1)
        PFL2(14)  PREF(a6, b6, 6)  CONS(a2, b2, 2)
        PFL2(15)  PREF(a7, b7, 7)  CONS(a3, b3, 3)

        if (s + 1 < N_SUPER) {
            PFL2(16)  PREF(a0, b0, 8)   CONS(a4, b4, 4)
            PFL2(17)  PREF(a1, b1, 9)   CONS(a5, b5, 5)
            PFL2(18)  PREF(a2, b2, 10)  CONS(a6, b6, 6)
            PFL2(19)  PREF(a3, b3, 11)  CONS(a7, b7, 7)
        } else {
            CONS(a4, b4, 4)
            CONS(a5, b5, 5)
            CONS(a6, b6, 6)
            CONS(a7, b7, 7)
        }

        ap  += 8 * U * STRIDE;
        bp  += 8 * U * STRIDE;
        op  += 8 * U * STRIDE;
        pfa += 8 * U * STRIDE;
        pfb += 8 * U * STRIDE;
    }
}

extern "C" void kernel_launch(void* const* d_in, const int* in_sizes, int n_in,
                              void* d_out, int out_size) {
    const float* a = (const float*)d_in[0];
    const float* b = (const float*)d_in[1];
    float* out = (float*)d_out;
    (void)in_sizes; (void)n_in; (void)out_size;

    ParallelScan_37374805409922_kernel<<<GRID, BLOCK>>>(a, b, out);
}

// round 15
// speedup vs baseline: 1.0396x; 1.0094x over previous
#include <cuda_runtime.h>

// Shape: a, b, h : (B=2, S=2048, D=1024, N=16) fp32, row-major.
// h[t] = a[t]*h[t-1] + b[t] along S. B*D*N = 32768 independent channels,
// contiguous at fixed t; scan stride = D*N = 16384 floats.
//
// R14: the two independently-proven-best factors combined:
//   - shape grid=128 / block=256: empirically the minimum wall-vs-ncu replay
//     gap (2.5-3.6 us; all larger grids pay 11-24 us — consistent with
//     sustained-replay DVFS favoring 20 idle SMs, invisible to ncu's single
//     boosted launch)
//   - st.global.wt output stores: best kernel-internal times on record
//     (120.2 / 122.3 us ncu; wt keeps dirty output lines out of L2, away
//     from the read+prefetch stream)
//   - mechanism unchanged: demand __ldcs register pipeline U=8 / distance-4,
//     per-line prefetch.global.L2 at lead 12 groups.

static constexpr int S_LEN   = 2048;
static constexpr int STRIDE  = 1024 * 16;       // D*N floats between timesteps
static constexpr int CHANNELS = 2 * STRIDE;     // 32768
static constexpr int U       = 8;               // timesteps per group
static constexpr int N_GROUPS = S_LEN / U;      // 256
static constexpr int N_SUPER  = N_GROUPS / 8;   // 32 super-iterations
static constexpr int BLOCK   = 256;
static constexpr int PF_G    = 12;              // prefetch lead base (groups)

// Demand-load local group G (relative to current ap/bp) into buffers A/B.
#define PREF(A, B, G)                                            \
    _Pragma("unroll")                                            \
    for (int u = 0; u < U; u++) {                                \
        A[u] = __ldcs(ap + ((G) * U + u) * STRIDE);              \
        B[u] = __ldcs(bp + ((G) * U + u) * STRIDE);              \
    }

// Consume buffers A/B as local group G: serial FMA chain + write-through
// stores (no dirty L2 lines contending with the read/prefetch stream).
#define CONS(A, B, G)                                            \
    _Pragma("unroll")                                            \
    for (int u = 0; u < U; u++) {                                \
        h = fmaf(A[u], h, B[u]);                                 \
        asm volatile("st.global.wt.f32 [%0], %1;" ::             \
            "l"(op + ((G) * U + u) * STRIDE), "f"(h) : "memory");\
    }

// Per-line L2 prefetch of local group G (pfa/pfb pre-advanced by PF_G groups).
#define PFL2(G)                                                  \
    if ((s * 8 + (G)) < N_GROUPS) {                              \
        _Pragma("unroll")                                        \
        for (int u = 0; u < U; u++) {                            \
            asm volatile("prefetch.global.L2 [%0];" ::           \
                "l"(pfa + (((G) - PF_G) * U + u) * STRIDE));     \
            asm volatile("prefetch.global.L2 [%0];" ::           \
                "l"(pfb + (((G) - PF_G) * U + u) * STRIDE));     \
        }                                                        \
    }

__global__ __launch_bounds__(BLOCK, 1)
void ParallelScan_37374805409922_kernel(const float* __restrict__ a,
                                        const float* __restrict__ b,
                                        float* __restrict__ out) {
    const int idx   = blockIdx.x * BLOCK + threadIdx.x;        // 0..32767
    const int batch = idx >> 14;                               // / 16384
    const int col   = idx & (STRIDE - 1);
    const size_t base = (size_t)batch * S_LEN * STRIDE + col;

    const float* __restrict__ ap = a + base;
    const float* __restrict__ bp = b + base;
    float* __restrict__ op = out + base;

    const float* pfa = ap + PF_G * U * STRIDE;
    const float* pfb = bp + PF_G * U * STRIDE;

    float a0[U], b0[U], a1[U], b1[U], a2[U], b2[U], a3[U], b3[U];
    float a4[U], b4[U], a5[U], b5[U], a6[U], b6[U], a7[U], b7[U];
    float h = 0.0f;

    // Prologue: demand-load 4 groups (prefetch window warms up organically).
    PREF(a0, b0, 0)
    PREF(a1, b1, 1)
    PREF(a2, b2, 2)
    PREF(a3, b3, 3)

    #pragma unroll 1
    for (int s = 0; s < N_SUPER; s++) {
        // Each slot: L2-prefetch 12 groups ahead, demand-load 4 ahead,
        // consume current.
        PFL2(12)  PREF(a4, b4, 4)  CONS(a0, b0, 0)
        PFL2(13)  PREF(a5, b5, 5)  CONS(a1, b1, 1)
        PFL2(14)  PREF(a6, b6, 6)  CONS(a2, b2, 2)
        PFL2(15)  PREF(a7, b7, 7)  CONS(a3, b3, 3)

        if (s + 1 < N_SUPER) {
            PFL2(16)  PREF(a0, b0, 8)   CONS(a4, b4, 4)
            PFL2(17)  PREF(a1, b1, 9)   CONS(a5, b5, 5)
            PFL2(18)  PREF(a2, b2, 10)  CONS(a6, b6, 6)
            PFL2(19)  PREF(a3, b3, 11)  CONS(a7, b7, 7)
        } else {
            CONS(a4, b4, 4)
            CONS(a5, b5, 5)
            CONS(a6, b6, 6)
            CONS(a7, b7, 7)
        }

        ap  += 8 * U * STRIDE;
        bp  += 8 * U * STRIDE;
        op  += 8 * U * STRIDE;
        pfa += 8 * U * STRIDE;
        pfb += 8 * U * STRIDE;
    }
}

extern "C" void kernel_launch(void* const* d_in, const int* in_sizes, int n_in,
                              void* d_out, int out_size) {
    const float* a = (const float*)d_in[0];
    const float* b = (const float*)d_in[1];
    float* out = (float*)d_out;
    (void)in_sizes; (void)n_in; (void)out_size;

    ParallelScan_37374805409922_kernel<<<CHANNELS / BLOCK, BLOCK>>>(a, b, out);
}